// round 14
// baseline (speedup 1.0000x reference)
#include <cuda_runtime.h>
#include <cuda_bf16.h>
#include <cstdint>

#define N_NODES 16384
#define N_EDGES 131072
#define F_IN 6
#define S_DIM 4
#define G_NUM 256
#define HH 30
#define C1 32
#define C2 64
#define C3 32

#define K1MAIN (HH * F_IN)      // 180
#define K1TOT  (K1MAIN + F_IN)  // 186
#define K1PAD  192
#define NKC1   (K1PAD / 16)     // 12
#define K2MAIN (HH * C1)        // 960
#define K2TOT  (K2MAIN + C1)    // 992
#define K2PAD  992
#define NKC2   (K2PAD / 16)     // 62

typedef unsigned long long ull;

// ---------------- scratch (no cudaMalloc allowed) ----------------
__device__ float g_B1[N_NODES * C1];
__device__ float g_B2[N_NODES * C2];
__device__ float g_XW[N_NODES * C3];
__device__ float g_B3[N_NODES * C3];
__device__ float g_H2A[N_EDGES * 32];     // layer-1 edge MLP output (padded)
__device__ float g_H2B[N_EDGES * 32];     // layer-2 edge MLP output (padded)
__device__ uint4 g_WTP1[NKC1 * C1 * 4];   // fragment-packed {bh0,bh1,bl0,bl1}
__device__ uint4 g_WTP2[NKC2 * C2 * 4];

// ---------------- helpers ----------------
__device__ __forceinline__ void red4(float* p, float a, float b, float c, float d) {
    asm volatile("red.global.add.v4.f32 [%0], {%1, %2, %3, %4};"
                 :: "l"(p), "f"(a), "f"(b), "f"(c), "f"(d) : "memory");
}
__device__ __forceinline__ void red2(float* p, float a, float b) {
    asm volatile("red.global.add.v2.f32 [%0], {%1, %2};"
                 :: "l"(p), "f"(a), "f"(b) : "memory");
}
__device__ __forceinline__ ull pk2(float a, float b) {
    ull r; asm("mov.b64 %0, {%1, %2};" : "=l"(r) : "f"(a), "f"(b)); return r;
}
__device__ __forceinline__ void upk2(ull p, float& a, float& b) {
    asm("mov.b64 {%0, %1}, %2;" : "=f"(a), "=f"(b) : "l"(p));
}
__device__ __forceinline__ ull mul2(ull a, ull b) {
    ull r; asm("mul.rn.f32x2 %0, %1, %2;" : "=l"(r) : "l"(a), "l"(b)); return r;
}
__device__ __forceinline__ ull sub2(ull a, ull b) {
    ull r; asm("sub.rn.f32x2 %0, %1, %2;" : "=l"(r) : "l"(a), "l"(b)); return r;
}
// pack (pA -> low half, pB -> high half) as bf16x2 hi, and residual lo
__device__ __forceinline__ void splitpair(uint32_t& h, uint32_t& l, float pA, float pB) {
    asm("cvt.rn.bf16x2.f32 %0, %1, %2;" : "=r"(h) : "f"(pB), "f"(pA));
    float rA = pA - __uint_as_float(h << 16);
    float rB = pB - __uint_as_float(h & 0xffff0000u);
    asm("cvt.rn.bf16x2.f32 %0, %1, %2;" : "=r"(l) : "f"(rB), "f"(rA));
}
// same but input is a packed f32x2 product; residual via sub.f32x2
__device__ __forceinline__ void splitpk(uint32_t& h, uint32_t& l, ull p) {
    float pA, pB; upk2(p, pA, pB);
    asm("cvt.rn.bf16x2.f32 %0, %1, %2;" : "=r"(h) : "f"(pB), "f"(pA));
    float hA = __uint_as_float(h << 16);
    float hB = __uint_as_float(h & 0xffff0000u);
    ull r = sub2(p, pk2(hA, hB));
    float rA, rB; upk2(r, rA, rB);
    asm("cvt.rn.bf16x2.f32 %0, %1, %2;" : "=r"(l) : "f"(rB), "f"(rA));
}
__device__ __forceinline__ void mma_bf16(float* c, const uint32_t* a, uint32_t b0, uint32_t b1) {
    asm volatile("mma.sync.aligned.m16n8k16.row.col.f32.bf16.bf16.f32 "
                 "{%0,%1,%2,%3}, {%4,%5,%6,%7}, {%8,%9}, {%0,%1,%2,%3};"
                 : "+f"(c[0]), "+f"(c[1]), "+f"(c[2]), "+f"(c[3])
                 : "r"(a[0]), "r"(a[1]), "r"(a[2]), "r"(a[3]), "r"(b0), "r"(b1));
}

// ---------------- weight prep ----------------
template <int C, int KMAIN, int KTOT, int NKC>
__global__ void prep_wt_kernel(const float* __restrict__ wk, const float* __restrict__ bk,
                               uint4* __restrict__ out)
{
    int idx = blockIdx.x * 256 + threadIdx.x;
    if (idx >= NKC * C * 4) return;
    int kc = idx / (C * 4);
    int rem = idx - kc * (C * 4);
    int c = rem >> 2, q = rem & 3;
    int k0 = kc * 16 + q * 2;
    float v[4];
    #pragma unroll
    for (int t = 0; t < 4; t++) {
        int k = k0 + (t >> 1) * 8 + (t & 1);
        float x = 0.f;
        if (k < KMAIN)      x = __ldg(wk + (size_t)k * C + c);
        else if (k < KTOT)  x = __ldg(bk + (size_t)(k - KMAIN) * C + c);
        v[t] = x;
    }
    uint4 o;
    splitpair(o.x, o.z, v[0], v[1]);
    splitpair(o.y, o.w, v[2], v[3]);
    out[idx] = o;
}

// ---------------- per-layer edge MLP: h2 = relu(relu(e@w0+b0)@w1+b1) ----------------
struct M1Sm {
    float w0p[S_DIM * 32];
    float b0p[32];
    float b1p[32];
    float w1p[HH * 32];
};

__global__ __launch_bounds__(256) void mlp1_kernel(
    const float* __restrict__ e,
    const float* __restrict__ w0, const float* __restrict__ b0,
    const float* __restrict__ w1, const float* __restrict__ b1,
    float* __restrict__ h2g)
{
    __shared__ M1Sm S;
    const int tid = threadIdx.x;
    for (int j = tid; j < S_DIM * 32; j += 256) {
        int s = j >> 5, jj = j & 31;
        S.w0p[j] = (jj < HH) ? w0[s * HH + jj] : 0.f;
    }
    for (int j = tid; j < HH * 32; j += 256) {
        int h = j >> 5, jj = j & 31;
        S.w1p[j] = (jj < HH) ? w1[h * HH + jj] : 0.f;
    }
    if (tid < 32) {
        S.b0p[tid] = (tid < HH) ? b0[tid] : 0.f;
        S.b1p[tid] = (tid < HH) ? b1[tid] : 0.f;
    }
    __syncthreads();

    const int i = blockIdx.x * 256 + tid;
    float4 ef = __ldg((const float4*)e + i);
    float ev[4] = {ef.x, ef.y, ef.z, ef.w};

    float h1[32];
    #pragma unroll
    for (int jb = 0; jb < 8; jb++) {
        float4 a = *(const float4*)&S.b0p[jb * 4];
        #pragma unroll
        for (int s = 0; s < S_DIM; s++) {
            float4 w = *(const float4*)&S.w0p[s * 32 + jb * 4];
            a.x += ev[s] * w.x; a.y += ev[s] * w.y;
            a.z += ev[s] * w.z; a.w += ev[s] * w.w;
        }
        h1[jb * 4 + 0] = fmaxf(a.x, 0.f); h1[jb * 4 + 1] = fmaxf(a.y, 0.f);
        h1[jb * 4 + 2] = fmaxf(a.z, 0.f); h1[jb * 4 + 3] = fmaxf(a.w, 0.f);
    }
    float* dst = h2g + (size_t)i * 32;
    #pragma unroll
    for (int jb = 0; jb < 8; jb++) {
        float4 a = *(const float4*)&S.b1p[jb * 4];
        #pragma unroll
        for (int h = 0; h < HH; h++) {
            float4 w = *(const float4*)&S.w1p[h * 32 + jb * 4];
            a.x += h1[h] * w.x; a.y += h1[h] * w.y;
            a.z += h1[h] * w.z; a.w += h1[h] * w.w;
        }
        *(float4*)(dst + jb * 4) = make_float4(fmaxf(a.x, 0.f), fmaxf(a.y, 0.f),
                                               fmaxf(a.z, 0.f), fmaxf(a.w, 0.f));
    }
}

// ---------------- ECC layer: h2-tile load + gather + bf16 3-MMA GEMM + scatter ----------------
template <int XSTR>
struct ESm {
    float h2[256 * 36];
    float xs[256 * XSTR];
};

template <int F, int C, int NKC, bool RELU_IN, int MINCTA>
__global__ __launch_bounds__(256, MINCTA) void ecc_mma_kernel(
    const float* __restrict__ xin, const float* __restrict__ h2g,
    const int* __restrict__ src, const int* __restrict__ tgt,
    const uint4* __restrict__ wtp,
    float* __restrict__ agg)
{
    constexpr int NT = 256, TM = 256;
    constexpr int XSTR = (F == 32) ? 36 : 8;
    constexpr int NNT = C / 8;
    constexpr int KMAIN = HH * F;
    constexpr int KTOT = KMAIN + F;

    extern __shared__ __align__(16) char smraw[];
    ESm<XSTR>& S = *reinterpret_cast<ESm<XSTR>*>(smraw);

    const int tid = threadIdx.x;
    const int i0 = blockIdx.x * TM;

    // --- load h2 tile (coalesced, global stride 32 -> smem stride 36) ---
    #pragma unroll
    for (int t = 0; t < 8; t++) {
        int j = tid + t * NT;
        int i = j >> 3, q = j & 7;
        float4 v = __ldg((const float4*)(h2g + (size_t)(i0 + i) * 32) + q);
        *(float4*)&S.h2[i * 36 + q * 4] = v;
    }
    // --- gather x[src] ---
    if constexpr (F == 32) {
        #pragma unroll
        for (int t = 0; t < 8; t++) {
            int j = tid + t * NT;
            int i = j >> 3, q = j & 7;
            int s = __ldg(src + i0 + i);
            float4 v = __ldg((const float4*)(xin + (size_t)s * F) + q);
            if (RELU_IN) { v.x = fmaxf(v.x, 0.f); v.y = fmaxf(v.y, 0.f);
                           v.z = fmaxf(v.z, 0.f); v.w = fmaxf(v.w, 0.f); }
            *(float4*)(S.xs + i * XSTR + q * 4) = v;
        }
    } else {
        #pragma unroll
        for (int t = 0; t < (TM * F) / NT; t++) {
            int j = tid + t * NT;
            int i = j / F, f = j - i * F;
            int s = __ldg(src + i0 + i);
            float v = __ldg(xin + (size_t)s * F + f);
            S.xs[i * XSTR + f] = RELU_IN ? fmaxf(v, 0.f) : v;
        }
    }
    __syncthreads();

    // --- warp-tile GEMM: warp covers rows [32w, 32w+32) x all C (2 m16 tiles) ---
    const int lane = tid & 31, wid = tid >> 5;
    const int qr = lane >> 2;
    const int kq = lane & 3;
    const int ka = kq * 2;
    const int rr[4] = { wid * 32 + qr, wid * 32 + qr + 8,
                        wid * 32 + qr + 16, wid * 32 + qr + 24 };

    float acc[2][NNT][4];
    #pragma unroll
    for (int m = 0; m < 2; m++)
        #pragma unroll
        for (int nt = 0; nt < NNT; nt++) {
            acc[m][nt][0] = 0.f; acc[m][nt][1] = 0.f;
            acc[m][nt][2] = 0.f; acc[m][nt][3] = 0.f;
        }

    for (int kc = 0; kc < NKC; kc++) {
        uint32_t ah[2][4], al[2][4];
        if constexpr (F == 32) {
            ull hs2[4];
            if (kc < KMAIN / 16) {
                #pragma unroll
                for (int m = 0; m < 4; m++) {
                    float h = S.h2[rr[m] * 36 + (kc >> 1)];
                    hs2[m] = pk2(h, h);
                }
            } else {
                #pragma unroll
                for (int m = 0; m < 4; m++) hs2[m] = pk2(1.f, 1.f);
            }
            const int f0 = (kc & 1) * 16;
            #pragma unroll
            for (int m = 0; m < 2; m++) {
                ull xa0 = *(const ull*)(S.xs + rr[2 * m] * XSTR + f0 + ka);
                ull xa8 = *(const ull*)(S.xs + rr[2 * m] * XSTR + f0 + ka + 8);
                ull xb0 = *(const ull*)(S.xs + rr[2 * m + 1] * XSTR + f0 + ka);
                ull xb8 = *(const ull*)(S.xs + rr[2 * m + 1] * XSTR + f0 + ka + 8);
                splitpk(ah[m][0], al[m][0], mul2(hs2[2 * m], xa0));
                splitpk(ah[m][1], al[m][1], mul2(hs2[2 * m + 1], xb0));
                splitpk(ah[m][2], al[m][2], mul2(hs2[2 * m], xa8));
                splitpk(ah[m][3], al[m][3], mul2(hs2[2 * m + 1], xb8));
            }
        } else {
            float p[4][4];
            const int kb = kc * 16 + ka;
            #pragma unroll
            for (int jj = 0; jj < 2; jj++) {
                #pragma unroll
                for (int dd = 0; dd < 2; dd++) {
                    int k = kb + jj * 8 + dd;
                    #pragma unroll
                    for (int m = 0; m < 4; m++) {
                        float v = 0.f;
                        if (k < KMAIN) {
                            int h = k / F, f = k - h * F;
                            v = S.h2[rr[m] * 36 + h] * S.xs[rr[m] * XSTR + f];
                        } else if (k < KTOT) {
                            v = S.xs[rr[m] * XSTR + (k - KMAIN)];
                        }
                        p[m][jj * 2 + dd] = v;
                    }
                }
            }
            #pragma unroll
            for (int m = 0; m < 2; m++) {
                splitpair(ah[m][0], al[m][0], p[2 * m][0], p[2 * m][1]);
                splitpair(ah[m][1], al[m][1], p[2 * m + 1][0], p[2 * m + 1][1]);
                splitpair(ah[m][2], al[m][2], p[2 * m][2], p[2 * m][3]);
                splitpair(ah[m][3], al[m][3], p[2 * m + 1][2], p[2 * m + 1][3]);
            }
        }

        #pragma unroll
        for (int nt = 0; nt < NNT; nt++) {
            uint4 bf = __ldg(&wtp[(size_t)(kc * C + nt * 8 + qr) * 4 + kq]);
            #pragma unroll
            for (int m = 0; m < 2; m++) {
                mma_bf16(acc[m][nt], ah[m], bf.x, bf.y);
                mma_bf16(acc[m][nt], al[m], bf.x, bf.y);
                mma_bf16(acc[m][nt], ah[m], bf.z, bf.w);
            }
        }
    }

    // --- scatter-add to agg[tgt] ---
    #pragma unroll
    for (int m = 0; m < 2; m++) {
        int t0 = __ldg(tgt + i0 + rr[2 * m]);
        int t1 = __ldg(tgt + i0 + rr[2 * m + 1]);
        float* d0 = agg + (size_t)t0 * C + ka;
        float* d1 = agg + (size_t)t1 * C + ka;
        #pragma unroll
        for (int nt = 0; nt < NNT; nt++) {
            red2(d0 + nt * 8, acc[m][nt][0], acc[m][nt][1]);
            red2(d1 + nt * 8, acc[m][nt][2], acc[m][nt][3]);
        }
    }
}

// ---------------- staged node GEMM (F%4==0): out = [bias] + relu?(x)@root; opt. self-loop ----------------
template <int F, int C, bool BIAS, bool RELU_IN, bool SELF>
__global__ __launch_bounds__(256) void base_tile_kernel(
    const float* __restrict__ x, const float* __restrict__ root,
    const float* __restrict__ bias, const float* __restrict__ gw_self,
    float* __restrict__ out, float* __restrict__ b3)
{
    constexpr int NB = 64;
    constexpr int XP = F + 1;
    __shared__ float sx[NB * XP];
    __shared__ float sroot[F * C];
    __shared__ float sb[C];
    const int tid = threadIdx.x;
    const int n0 = blockIdx.x * NB;

    for (int j = tid; j < F * C; j += 256) sroot[j] = root[j];
    if (BIAS) { if (tid < C) sb[tid] = bias[tid]; }
    for (int j = tid; j < NB * (F / 4); j += 256) {
        int n = j / (F / 4), q = j - n * (F / 4);
        float4 v = __ldg((const float4*)(x + (size_t)(n0 + n) * F) + q);
        if (RELU_IN) { v.x = fmaxf(v.x, 0.f); v.y = fmaxf(v.y, 0.f);
                       v.z = fmaxf(v.z, 0.f); v.w = fmaxf(v.w, 0.f); }
        float* d = sx + n * XP + q * 4;
        d[0] = v.x; d[1] = v.y; d[2] = v.z; d[3] = v.w;
    }
    __syncthreads();

    for (int j = tid; j < NB * (C / 4); j += 256) {
        int n = j / (C / 4), q = (j - n * (C / 4)) * 4;
        float4 a = BIAS ? make_float4(sb[q], sb[q + 1], sb[q + 2], sb[q + 3])
                        : make_float4(0.f, 0.f, 0.f, 0.f);
        const float* xr = sx + n * XP;
        #pragma unroll
        for (int f = 0; f < F; f++) {
            float xv = xr[f];
            float4 rv = *(const float4*)&sroot[f * C + q];
            a.x += xv * rv.x; a.y += xv * rv.y; a.z += xv * rv.z; a.w += xv * rv.w;
        }
        *(float4*)(out + (size_t)(n0 + n) * C + q) = a;
        if (SELF) {
            float w = __ldg(gw_self + n0 + n);
            *(float4*)(b3 + (size_t)(n0 + n) * C + q) =
                make_float4(w * a.x, w * a.y, w * a.z, w * a.w);
        }
    }
}

// ---------------- simple node GEMM (F=6 case) ----------------
template <int F, int C, bool BIAS>
__global__ __launch_bounds__(256) void base2_kernel(
    const float* __restrict__ x, const float* __restrict__ root,
    const float* __restrict__ bias, float* __restrict__ out)
{
    __shared__ float sroot[F * C];
    __shared__ float sb[C];
    const int tid = threadIdx.x;
    for (int j = tid; j < F * C; j += 256) sroot[j] = root[j];
    if (BIAS) { if (tid < C) sb[tid] = bias[tid]; }
    __syncthreads();

    constexpr int QC = C / 4;
    int idx = blockIdx.x * 256 + tid;
    int n = idx / QC, q = (idx - n * QC) * 4;
    if (n >= N_NODES) return;

    float4 a = BIAS ? make_float4(sb[q], sb[q + 1], sb[q + 2], sb[q + 3])
                    : make_float4(0.f, 0.f, 0.f, 0.f);
    const float* xr = x + (size_t)n * F;
    #pragma unroll
    for (int f = 0; f < F; f++) {
        float xv = __ldg(xr + f);
        float4 rv = *(const float4*)&sroot[f * C + q];
        a.x += xv * rv.x; a.y += xv * rv.y; a.z += xv * rv.z; a.w += xv * rv.w;
    }
    *(float4*)(out + (size_t)n * C + q) = a;
}

__global__ void zero_kernel(float* __restrict__ buf, int n)
{
    int i = blockIdx.x * blockDim.x + threadIdx.x;
    if (i < n) buf[i] = 0.f;
}

// GCN weighted SpMM over real edges only (self loops fused into XW kernel)
__global__ void gcn_edge_kernel(const float* __restrict__ xw,
                                const int* __restrict__ gs, const int* __restrict__ gt,
                                const float* __restrict__ gw, float* __restrict__ b3)
{
    int idx = blockIdx.x * blockDim.x + threadIdx.x;
    int m = idx >> 3, q = (idx & 7) * 4;
    if (m >= N_EDGES) return;
    float w = __ldg(gw + m);
    float4 v = __ldg((const float4*)(xw + (size_t)__ldg(gs + m) * C3 + q));
    red4(b3 + (size_t)__ldg(gt + m) * C3 + q, w * v.x, w * v.y, w * v.z, w * v.w);
}

// x3 = relu(b3 + gcn_b); out[seg[n], :] += x3[n, :]
__global__ void pool_kernel(const float* __restrict__ b3, const float* __restrict__ gb,
                            const int* __restrict__ seg, float* __restrict__ out)
{
    int idx = blockIdx.x * blockDim.x + threadIdx.x;
    int n = idx >> 3, q = (idx & 7) * 4;
    if (n >= N_NODES) return;
    float4 v = *(const float4*)(b3 + (size_t)n * C3 + q);
    float a = fmaxf(v.x + __ldg(gb + q), 0.f);
    float b = fmaxf(v.y + __ldg(gb + q + 1), 0.f);
    float c = fmaxf(v.z + __ldg(gb + q + 2), 0.f);
    float d = fmaxf(v.w + __ldg(gb + q + 3), 0.f);
    red4(out + (size_t)__ldg(seg + n) * C3 + q, a, b, c, d);
}

// ---------------- launch ----------------
extern "C" void kernel_launch(void* const* d_in, const int* in_sizes, int n_in,
                              void* d_out, int out_size)
{
    (void)in_sizes; (void)n_in; (void)out_size;
    const float* x     = (const float*)d_in[0];
    const float* e     = (const float*)d_in[1];
    const int*   src   = (const int*)d_in[2];
    const int*   tgt   = (const int*)d_in[3];
    const int*   seg   = (const int*)d_in[4];
    const int*   gsrc  = (const int*)d_in[5];
    const int*   gtgt  = (const int*)d_in[6];
    const float* gw    = (const float*)d_in[7];
    const float* e1_w0 = (const float*)d_in[8];
    const float* e1_b0 = (const float*)d_in[9];
    const float* e1_w1 = (const float*)d_in[10];
    const float* e1_b1 = (const float*)d_in[11];
    const float* e1_wk = (const float*)d_in[12];
    const float* e1_bk = (const float*)d_in[13];
    const float* e1_root = (const float*)d_in[14];
    const float* e1_bias = (const float*)d_in[15];
    const float* e2_w0 = (const float*)d_in[16];
    const float* e2_b0 = (const float*)d_in[17];
    const float* e2_w1 = (const float*)d_in[18];
    const float* e2_b1 = (const float*)d_in[19];
    const float* e2_wk = (const float*)d_in[20];
    const float* e2_bk = (const float*)d_in[21];
    const float* e2_root = (const float*)d_in[22];
    const float* e2_bias = (const float*)d_in[23];
    const float* gcn_W = (const float*)d_in[24];
    const float* gcn_b = (const float*)d_in[25];
    float* out = (float*)d_out;

    float *B1, *B2, *XW, *B3, *H2A, *H2B;
    uint4 *WTP1, *WTP2;
    cudaGetSymbolAddress((void**)&B1, g_B1);
    cudaGetSymbolAddress((void**)&B2, g_B2);
    cudaGetSymbolAddress((void**)&XW, g_XW);
    cudaGetSymbolAddress((void**)&B3, g_B3);
    cudaGetSymbolAddress((void**)&H2A, g_H2A);
    cudaGetSymbolAddress((void**)&H2B, g_H2B);
    cudaGetSymbolAddress((void**)&WTP1, g_WTP1);
    cudaGetSymbolAddress((void**)&WTP2, g_WTP2);

    const int smem1 = (int)sizeof(ESm<8>);
    const int smem2 = (int)sizeof(ESm<36>);
    cudaFuncSetAttribute((const void*)ecc_mma_kernel<F_IN, C1, NKC1, false, 3>,
                         cudaFuncAttributeMaxDynamicSharedMemorySize, smem1);
    cudaFuncSetAttribute((const void*)ecc_mma_kernel<C1, C2, NKC2, true, 3>,
                         cudaFuncAttributeMaxDynamicSharedMemorySize, smem2);

    // side stream (capture-forked).
    cudaStream_t s1;
    cudaStreamCreateWithFlags(&s1, cudaStreamNonBlocking);
    cudaEvent_t evF, ev1, ev2, ev3;
    cudaEventCreateWithFlags(&evF, cudaEventDisableTiming);
    cudaEventCreateWithFlags(&ev1, cudaEventDisableTiming);
    cudaEventCreateWithFlags(&ev2, cudaEventDisableTiming);
    cudaEventCreateWithFlags(&ev3, cudaEventDisableTiming);

    // fork
    cudaEventRecord(evF, 0);
    cudaStreamWaitEvent(s1, evF, 0);

    // s1 branch: edge-MLP layer 1 + prep1 (gates ecc1), then layer 2 + prep2, then zero(out)
    prep_wt_kernel<C1, K1MAIN, K1TOT, NKC1><<<(NKC1 * C1 * 4 + 255) / 256, 256, 0, s1>>>(e1_wk, e1_bk, WTP1);
    mlp1_kernel<<<N_EDGES / 256, 256, 0, s1>>>(e, e1_w0, e1_b0, e1_w1, e1_b1, H2A);
    cudaEventRecord(ev1, s1);
    prep_wt_kernel<C2, K2MAIN, K2TOT, NKC2><<<(NKC2 * C2 * 4 + 255) / 256, 256, 0, s1>>>(e2_wk, e2_bk, WTP2);
    mlp1_kernel<<<N_EDGES / 256, 256, 0, s1>>>(e, e2_w0, e2_b0, e2_w1, e2_b1, H2B);
    cudaEventRecord(ev2, s1);
    zero_kernel<<<(G_NUM * C3 + 255) / 256, 256, 0, s1>>>(out, G_NUM * C3);
    cudaEventRecord(ev3, s1);

    // main chain on stream 0
    base2_kernel<F_IN, C1, true><<<(N_NODES * (C1 / 4) + 255) / 256, 256>>>(x, e1_root, e1_bias, B1);
    cudaStreamWaitEvent(0, ev1, 0);
    ecc_mma_kernel<F_IN, C1, NKC1, false, 3><<<N_EDGES / 256, 256, smem1>>>(
        x, H2A, src, tgt, WTP1, B1);

    base_tile_kernel<C1, C2, true, true, false><<<N_NODES / 64, 256>>>(
        B1, e2_root, e2_bias, nullptr, B2, nullptr);
    cudaStreamWaitEvent(0, ev2, 0);
    ecc_mma_kernel<C1, C2, NKC2, true, 3><<<N_EDGES / 256, 256, smem2>>>(
        B1, H2B, src, tgt, WTP2, B2);

    base_tile_kernel<C2, C3, false, true, true><<<N_NODES / 64, 256>>>(
        B2, gcn_W, nullptr, gw + N_EDGES, XW, B3);
    gcn_edge_kernel<<<(N_EDGES * 8 + 255) / 256, 256>>>(XW, gsrc, gtgt, gw, B3);

    cudaStreamWaitEvent(0, ev3, 0);
    pool_kernel<<<(N_NODES * 8 + 255) / 256, 256>>>(B3, gcn_b, seg, out);

    cudaEventDestroy(evF); cudaEventDestroy(ev1);
    cudaEventDestroy(ev2); cudaEventDestroy(ev3);
    cudaStreamDestroy(s1);
}

// round 16
// speedup vs baseline: 1.5437x; 1.5437x over previous
#include <cuda_runtime.h>
#include <cuda_bf16.h>
#include <cstdint>

#define N_NODES 16384
#define N_EDGES 131072
#define F_IN 6
#define S_DIM 4
#define G_NUM 256
#define HH 30
#define C1 32
#define C2 64
#define C3 32

#define K1MAIN (HH * F_IN)      // 180
#define K1TOT  (K1MAIN + F_IN)  // 186
#define K1PAD  192
#define NKC1   (K1PAD / 16)     // 12
#define K2MAIN (HH * C1)        // 960
#define K2TOT  (K2MAIN + C1)    // 992
#define K2PAD  992
#define NKC2   (K2PAD / 16)     // 62

typedef unsigned long long ull;

// ---------------- scratch (no cudaMalloc allowed) ----------------
__device__ float g_B1[N_NODES * C1];
__device__ float g_B2[N_NODES * C2];
__device__ float g_XW[N_NODES * C3];
__device__ float g_B3[N_NODES * C3];
__device__ float g_H2A[N_EDGES * 32];     // layer-1 edge MLP output (padded)
__device__ float g_H2B[N_EDGES * 32];     // layer-2 edge MLP output (padded)
__device__ uint4 g_WTP1[NKC1 * C1 * 4];   // fragment-packed {bh0,bh1,bl0,bl1}
__device__ uint4 g_WTP2[NKC2 * C2 * 4];

// ---------------- helpers ----------------
__device__ __forceinline__ void red4(float* p, float a, float b, float c, float d) {
    asm volatile("red.global.add.v4.f32 [%0], {%1, %2, %3, %4};"
                 :: "l"(p), "f"(a), "f"(b), "f"(c), "f"(d) : "memory");
}
__device__ __forceinline__ void red2(float* p, float a, float b) {
    asm volatile("red.global.add.v2.f32 [%0], {%1, %2};"
                 :: "l"(p), "f"(a), "f"(b) : "memory");
}
__device__ __forceinline__ ull pk2(float a, float b) {
    ull r; asm("mov.b64 %0, {%1, %2};" : "=l"(r) : "f"(a), "f"(b)); return r;
}
__device__ __forceinline__ void upk2(ull p, float& a, float& b) {
    asm("mov.b64 {%0, %1}, %2;" : "=f"(a), "=f"(b) : "l"(p));
}
__device__ __forceinline__ ull mul2(ull a, ull b) {
    ull r; asm("mul.rn.f32x2 %0, %1, %2;" : "=l"(r) : "l"(a), "l"(b)); return r;
}
__device__ __forceinline__ ull sub2(ull a, ull b) {
    ull r; asm("sub.rn.f32x2 %0, %1, %2;" : "=l"(r) : "l"(a), "l"(b)); return r;
}
// pack (pA -> low half, pB -> high half) as bf16x2 hi, and residual lo
__device__ __forceinline__ void splitpair(uint32_t& h, uint32_t& l, float pA, float pB) {
    asm("cvt.rn.bf16x2.f32 %0, %1, %2;" : "=r"(h) : "f"(pB), "f"(pA));
    float rA = pA - __uint_as_float(h << 16);
    float rB = pB - __uint_as_float(h & 0xffff0000u);
    asm("cvt.rn.bf16x2.f32 %0, %1, %2;" : "=r"(l) : "f"(rB), "f"(rA));
}
// same but input is a packed f32x2 product; residual via sub.f32x2
__device__ __forceinline__ void splitpk(uint32_t& h, uint32_t& l, ull p) {
    float pA, pB; upk2(p, pA, pB);
    asm("cvt.rn.bf16x2.f32 %0, %1, %2;" : "=r"(h) : "f"(pB), "f"(pA));
    float hA = __uint_as_float(h << 16);
    float hB = __uint_as_float(h & 0xffff0000u);
    ull r = sub2(p, pk2(hA, hB));
    float rA, rB; upk2(r, rA, rB);
    asm("cvt.rn.bf16x2.f32 %0, %1, %2;" : "=r"(l) : "f"(rB), "f"(rA));
}
__device__ __forceinline__ void mma_bf16(float* c, const uint32_t* a, uint32_t b0, uint32_t b1) {
    asm volatile("mma.sync.aligned.m16n8k16.row.col.f32.bf16.bf16.f32 "
                 "{%0,%1,%2,%3}, {%4,%5,%6,%7}, {%8,%9}, {%0,%1,%2,%3};"
                 : "+f"(c[0]), "+f"(c[1]), "+f"(c[2]), "+f"(c[3])
                 : "r"(a[0]), "r"(a[1]), "r"(a[2]), "r"(a[3]), "r"(b0), "r"(b1));
}

// ---------------- weight prep ----------------
template <int C, int KMAIN, int KTOT, int NKC>
__global__ void prep_wt_kernel(const float* __restrict__ wk, const float* __restrict__ bk,
                               uint4* __restrict__ out)
{
    int idx = blockIdx.x * 256 + threadIdx.x;
    if (idx >= NKC * C * 4) return;
    int kc = idx / (C * 4);
    int rem = idx - kc * (C * 4);
    int c = rem >> 2, q = rem & 3;
    int k0 = kc * 16 + q * 2;
    float v[4];
    #pragma unroll
    for (int t = 0; t < 4; t++) {
        int k = k0 + (t >> 1) * 8 + (t & 1);
        float x = 0.f;
        if (k < KMAIN)      x = __ldg(wk + (size_t)k * C + c);
        else if (k < KTOT)  x = __ldg(bk + (size_t)(k - KMAIN) * C + c);
        v[t] = x;
    }
    uint4 o;
    splitpair(o.x, o.z, v[0], v[1]);
    splitpair(o.y, o.w, v[2], v[3]);
    out[idx] = o;
}

// ---------------- per-layer edge MLP: h2 = relu(relu(e@w0+b0)@w1+b1) ----------------
struct M1Sm {
    float w0p[S_DIM * 32];
    float b0p[32];
    float b1p[32];
    float w1p[HH * 32];
};

__global__ __launch_bounds__(256) void mlp1_kernel(
    const float* __restrict__ e,
    const float* __restrict__ w0, const float* __restrict__ b0,
    const float* __restrict__ w1, const float* __restrict__ b1,
    float* __restrict__ h2g)
{
    __shared__ M1Sm S;
    const int tid = threadIdx.x;
    for (int j = tid; j < S_DIM * 32; j += 256) {
        int s = j >> 5, jj = j & 31;
        S.w0p[j] = (jj < HH) ? w0[s * HH + jj] : 0.f;
    }
    for (int j = tid; j < HH * 32; j += 256) {
        int h = j >> 5, jj = j & 31;
        S.w1p[j] = (jj < HH) ? w1[h * HH + jj] : 0.f;
    }
    if (tid < 32) {
        S.b0p[tid] = (tid < HH) ? b0[tid] : 0.f;
        S.b1p[tid] = (tid < HH) ? b1[tid] : 0.f;
    }
    __syncthreads();

    const int i = blockIdx.x * 256 + tid;
    float4 ef = __ldg((const float4*)e + i);
    float ev[4] = {ef.x, ef.y, ef.z, ef.w};

    float h1[32];
    #pragma unroll
    for (int jb = 0; jb < 8; jb++) {
        float4 a = *(const float4*)&S.b0p[jb * 4];
        #pragma unroll
        for (int s = 0; s < S_DIM; s++) {
            float4 w = *(const float4*)&S.w0p[s * 32 + jb * 4];
            a.x += ev[s] * w.x; a.y += ev[s] * w.y;
            a.z += ev[s] * w.z; a.w += ev[s] * w.w;
        }
        h1[jb * 4 + 0] = fmaxf(a.x, 0.f); h1[jb * 4 + 1] = fmaxf(a.y, 0.f);
        h1[jb * 4 + 2] = fmaxf(a.z, 0.f); h1[jb * 4 + 3] = fmaxf(a.w, 0.f);
    }
    float* dst = h2g + (size_t)i * 32;
    #pragma unroll
    for (int jb = 0; jb < 8; jb++) {
        float4 a = *(const float4*)&S.b1p[jb * 4];
        #pragma unroll
        for (int h = 0; h < HH; h++) {
            float4 w = *(const float4*)&S.w1p[h * 32 + jb * 4];
            a.x += h1[h] * w.x; a.y += h1[h] * w.y;
            a.z += h1[h] * w.z; a.w += h1[h] * w.w;
        }
        *(float4*)(dst + jb * 4) = make_float4(fmaxf(a.x, 0.f), fmaxf(a.y, 0.f),
                                               fmaxf(a.z, 0.f), fmaxf(a.w, 0.f));
    }
}

// ---------------- ECC layer: h2-tile load + gather + bf16 3-MMA GEMM + scatter ----------------
template <int XSTR>
struct ESm {
    float h2[256 * 36];
    float xs[256 * XSTR];
};

template <int F, int C, int NKC, bool RELU_IN, int MINCTA>
__global__ __launch_bounds__(256, MINCTA) void ecc_mma_kernel(
    const float* __restrict__ xin, const float* __restrict__ h2g,
    const int* __restrict__ src, const int* __restrict__ tgt,
    const uint4* __restrict__ wtp,
    float* __restrict__ agg)
{
    constexpr int NT = 256, TM = 256;
    constexpr int XSTR = (F == 32) ? 36 : 8;
    constexpr int NNT = C / 8;
    constexpr int KMAIN = HH * F;
    constexpr int KTOT = KMAIN + F;

    extern __shared__ __align__(16) char smraw[];
    ESm<XSTR>& S = *reinterpret_cast<ESm<XSTR>*>(smraw);

    const int tid = threadIdx.x;
    const int i0 = blockIdx.x * TM;

    // --- load h2 tile (coalesced, global stride 32 -> smem stride 36) ---
    #pragma unroll
    for (int t = 0; t < 8; t++) {
        int j = tid + t * NT;
        int i = j >> 3, q = j & 7;
        float4 v = __ldg((const float4*)(h2g + (size_t)(i0 + i) * 32) + q);
        *(float4*)&S.h2[i * 36 + q * 4] = v;
    }
    // --- gather x[src] ---
    if constexpr (F == 32) {
        #pragma unroll
        for (int t = 0; t < 8; t++) {
            int j = tid + t * NT;
            int i = j >> 3, q = j & 7;
            int s = __ldg(src + i0 + i);
            float4 v = __ldg((const float4*)(xin + (size_t)s * F) + q);
            if (RELU_IN) { v.x = fmaxf(v.x, 0.f); v.y = fmaxf(v.y, 0.f);
                           v.z = fmaxf(v.z, 0.f); v.w = fmaxf(v.w, 0.f); }
            *(float4*)(S.xs + i * XSTR + q * 4) = v;
        }
    } else {
        #pragma unroll
        for (int t = 0; t < (TM * F) / NT; t++) {
            int j = tid + t * NT;
            int i = j / F, f = j - i * F;
            int s = __ldg(src + i0 + i);
            float v = __ldg(xin + (size_t)s * F + f);
            S.xs[i * XSTR + f] = RELU_IN ? fmaxf(v, 0.f) : v;
        }
    }
    __syncthreads();

    // --- warp-tile GEMM: warp covers rows [32w, 32w+32) x all C (2 m16 tiles) ---
    const int lane = tid & 31, wid = tid >> 5;
    const int qr = lane >> 2;
    const int kq = lane & 3;
    const int ka = kq * 2;
    const int rr[4] = { wid * 32 + qr, wid * 32 + qr + 8,
                        wid * 32 + qr + 16, wid * 32 + qr + 24 };

    float acc[2][NNT][4];
    #pragma unroll
    for (int m = 0; m < 2; m++)
        #pragma unroll
        for (int nt = 0; nt < NNT; nt++) {
            acc[m][nt][0] = 0.f; acc[m][nt][1] = 0.f;
            acc[m][nt][2] = 0.f; acc[m][nt][3] = 0.f;
        }

    #pragma unroll 2
    for (int kc = 0; kc < NKC; kc++) {
        uint32_t ah[2][4], al[2][4];
        if constexpr (F == 32) {
            ull hs2[4];
            if (kc < KMAIN / 16) {
                #pragma unroll
                for (int m = 0; m < 4; m++) {
                    float h = S.h2[rr[m] * 36 + (kc >> 1)];
                    hs2[m] = pk2(h, h);
                }
            } else {
                #pragma unroll
                for (int m = 0; m < 4; m++) hs2[m] = pk2(1.f, 1.f);
            }
            const int f0 = (kc & 1) * 16;
            #pragma unroll
            for (int m = 0; m < 2; m++) {
                ull xa0 = *(const ull*)(S.xs + rr[2 * m] * XSTR + f0 + ka);
                ull xa8 = *(const ull*)(S.xs + rr[2 * m] * XSTR + f0 + ka + 8);
                ull xb0 = *(const ull*)(S.xs + rr[2 * m + 1] * XSTR + f0 + ka);
                ull xb8 = *(const ull*)(S.xs + rr[2 * m + 1] * XSTR + f0 + ka + 8);
                splitpk(ah[m][0], al[m][0], mul2(hs2[2 * m], xa0));
                splitpk(ah[m][1], al[m][1], mul2(hs2[2 * m + 1], xb0));
                splitpk(ah[m][2], al[m][2], mul2(hs2[2 * m], xa8));
                splitpk(ah[m][3], al[m][3], mul2(hs2[2 * m + 1], xb8));
            }
        } else {
            float p[4][4];
            const int kb = kc * 16 + ka;
            #pragma unroll
            for (int jj = 0; jj < 2; jj++) {
                #pragma unroll
                for (int dd = 0; dd < 2; dd++) {
                    int k = kb + jj * 8 + dd;
                    #pragma unroll
                    for (int m = 0; m < 4; m++) {
                        float v = 0.f;
                        if (k < KMAIN) {
                            int h = k / F, f = k - h * F;
                            v = S.h2[rr[m] * 36 + h] * S.xs[rr[m] * XSTR + f];
                        } else if (k < KTOT) {
                            v = S.xs[rr[m] * XSTR + (k - KMAIN)];
                        }
                        p[m][jj * 2 + dd] = v;
                    }
                }
            }
            #pragma unroll
            for (int m = 0; m < 2; m++) {
                splitpair(ah[m][0], al[m][0], p[2 * m][0], p[2 * m][1]);
                splitpair(ah[m][1], al[m][1], p[2 * m + 1][0], p[2 * m + 1][1]);
                splitpair(ah[m][2], al[m][2], p[2 * m][2], p[2 * m][3]);
                splitpair(ah[m][3], al[m][3], p[2 * m + 1][2], p[2 * m + 1][3]);
            }
        }

        #pragma unroll
        for (int nt = 0; nt < NNT; nt++) {
            uint4 bf = __ldg(&wtp[(size_t)(kc * C + nt * 8 + qr) * 4 + kq]);
            #pragma unroll
            for (int m = 0; m < 2; m++) {
                mma_bf16(acc[m][nt], ah[m], bf.x, bf.y);
                mma_bf16(acc[m][nt], al[m], bf.x, bf.y);
                mma_bf16(acc[m][nt], ah[m], bf.z, bf.w);
            }
        }
    }

    // --- scatter-add to agg[tgt] ---
    #pragma unroll
    for (int m = 0; m < 2; m++) {
        int t0 = __ldg(tgt + i0 + rr[2 * m]);
        int t1 = __ldg(tgt + i0 + rr[2 * m + 1]);
        float* d0 = agg + (size_t)t0 * C + ka;
        float* d1 = agg + (size_t)t1 * C + ka;
        #pragma unroll
        for (int nt = 0; nt < NNT; nt++) {
            red2(d0 + nt * 8, acc[m][nt][0], acc[m][nt][1]);
            red2(d1 + nt * 8, acc[m][nt][2], acc[m][nt][3]);
        }
    }
}

// ---------------- staged node GEMM (F%4==0): out = [bias] + relu?(x)@root; opt. self-loop ----------------
template <int F, int C, bool BIAS, bool RELU_IN, bool SELF>
__global__ __launch_bounds__(256) void base_tile_kernel(
    const float* __restrict__ x, const float* __restrict__ root,
    const float* __restrict__ bias, const float* __restrict__ gw_self,
    float* __restrict__ out, float* __restrict__ b3)
{
    constexpr int NB = 64;
    constexpr int XP = F + 1;
    __shared__ float sx[NB * XP];
    __shared__ float sroot[F * C];
    __shared__ float sb[C];
    const int tid = threadIdx.x;
    const int n0 = blockIdx.x * NB;

    for (int j = tid; j < F * C; j += 256) sroot[j] = root[j];
    if (BIAS) { if (tid < C) sb[tid] = bias[tid]; }
    for (int j = tid; j < NB * (F / 4); j += 256) {
        int n = j / (F / 4), q = j - n * (F / 4);
        float4 v = __ldg((const float4*)(x + (size_t)(n0 + n) * F) + q);
        if (RELU_IN) { v.x = fmaxf(v.x, 0.f); v.y = fmaxf(v.y, 0.f);
                       v.z = fmaxf(v.z, 0.f); v.w = fmaxf(v.w, 0.f); }
        float* d = sx + n * XP + q * 4;
        d[0] = v.x; d[1] = v.y; d[2] = v.z; d[3] = v.w;
    }
    __syncthreads();

    for (int j = tid; j < NB * (C / 4); j += 256) {
        int n = j / (C / 4), q = (j - n * (C / 4)) * 4;
        float4 a = BIAS ? make_float4(sb[q], sb[q + 1], sb[q + 2], sb[q + 3])
                        : make_float4(0.f, 0.f, 0.f, 0.f);
        const float* xr = sx + n * XP;
        #pragma unroll
        for (int f = 0; f < F; f++) {
            float xv = xr[f];
            float4 rv = *(const float4*)&sroot[f * C + q];
            a.x += xv * rv.x; a.y += xv * rv.y; a.z += xv * rv.z; a.w += xv * rv.w;
        }
        *(float4*)(out + (size_t)(n0 + n) * C + q) = a;
        if (SELF) {
            float w = __ldg(gw_self + n0 + n);
            *(float4*)(b3 + (size_t)(n0 + n) * C + q) =
                make_float4(w * a.x, w * a.y, w * a.z, w * a.w);
        }
    }
}

// ---------------- simple node GEMM (F=6 case) ----------------
template <int F, int C, bool BIAS>
__global__ __launch_bounds__(256) void base2_kernel(
    const float* __restrict__ x, const float* __restrict__ root,
    const float* __restrict__ bias, float* __restrict__ out)
{
    __shared__ float sroot[F * C];
    __shared__ float sb[C];
    const int tid = threadIdx.x;
    for (int j = tid; j < F * C; j += 256) sroot[j] = root[j];
    if (BIAS) { if (tid < C) sb[tid] = bias[tid]; }
    __syncthreads();

    constexpr int QC = C / 4;
    int idx = blockIdx.x * 256 + tid;
    int n = idx / QC, q = (idx - n * QC) * 4;
    if (n >= N_NODES) return;

    float4 a = BIAS ? make_float4(sb[q], sb[q + 1], sb[q + 2], sb[q + 3])
                    : make_float4(0.f, 0.f, 0.f, 0.f);
    const float* xr = x + (size_t)n * F;
    #pragma unroll
    for (int f = 0; f < F; f++) {
        float xv = __ldg(xr + f);
        float4 rv = *(const float4*)&sroot[f * C + q];
        a.x += xv * rv.x; a.y += xv * rv.y; a.z += xv * rv.z; a.w += xv * rv.w;
    }
    *(float4*)(out + (size_t)n * C + q) = a;
}

__global__ void zero_kernel(float* __restrict__ buf, int n)
{
    int i = blockIdx.x * blockDim.x + threadIdx.x;
    if (i < n) buf[i] = 0.f;
}

// GCN weighted SpMM over real edges only (self loops fused into XW kernel)
__global__ void gcn_edge_kernel(const float* __restrict__ xw,
                                const int* __restrict__ gs, const int* __restrict__ gt,
                                const float* __restrict__ gw, float* __restrict__ b3)
{
    int idx = blockIdx.x * blockDim.x + threadIdx.x;
    int m = idx >> 3, q = (idx & 7) * 4;
    if (m >= N_EDGES) return;
    float w = __ldg(gw + m);
    float4 v = __ldg((const float4*)(xw + (size_t)__ldg(gs + m) * C3 + q));
    red4(b3 + (size_t)__ldg(gt + m) * C3 + q, w * v.x, w * v.y, w * v.z, w * v.w);
}

// x3 = relu(b3 + gcn_b); out[seg[n], :] += x3[n, :]
__global__ void pool_kernel(const float* __restrict__ b3, const float* __restrict__ gb,
                            const int* __restrict__ seg, float* __restrict__ out)
{
    int idx = blockIdx.x * blockDim.x + threadIdx.x;
    int n = idx >> 3, q = (idx & 7) * 4;
    if (n >= N_NODES) return;
    float4 v = *(const float4*)(b3 + (size_t)n * C3 + q);
    float a = fmaxf(v.x + __ldg(gb + q), 0.f);
    float b = fmaxf(v.y + __ldg(gb + q + 1), 0.f);
    float c = fmaxf(v.z + __ldg(gb + q + 2), 0.f);
    float d = fmaxf(v.w + __ldg(gb + q + 3), 0.f);
    red4(out + (size_t)__ldg(seg + n) * C3 + q, a, b, c, d);
}

// ---------------- launch ----------------
extern "C" void kernel_launch(void* const* d_in, const int* in_sizes, int n_in,
                              void* d_out, int out_size)
{
    (void)in_sizes; (void)n_in; (void)out_size;
    const float* x     = (const float*)d_in[0];
    const float* e     = (const float*)d_in[1];
    const int*   src   = (const int*)d_in[2];
    const int*   tgt   = (const int*)d_in[3];
    const int*   seg   = (const int*)d_in[4];
    const int*   gsrc  = (const int*)d_in[5];
    const int*   gtgt  = (const int*)d_in[6];
    const float* gw    = (const float*)d_in[7];
    const float* e1_w0 = (const float*)d_in[8];
    const float* e1_b0 = (const float*)d_in[9];
    const float* e1_w1 = (const float*)d_in[10];
    const float* e1_b1 = (const float*)d_in[11];
    const float* e1_wk = (const float*)d_in[12];
    const float* e1_bk = (const float*)d_in[13];
    const float* e1_root = (const float*)d_in[14];
    const float* e1_bias = (const float*)d_in[15];
    const float* e2_w0 = (const float*)d_in[16];
    const float* e2_b0 = (const float*)d_in[17];
    const float* e2_w1 = (const float*)d_in[18];
    const float* e2_b1 = (const float*)d_in[19];
    const float* e2_wk = (const float*)d_in[20];
    const float* e2_bk = (const float*)d_in[21];
    const float* e2_root = (const float*)d_in[22];
    const float* e2_bias = (const float*)d_in[23];
    const float* gcn_W = (const float*)d_in[24];
    const float* gcn_b = (const float*)d_in[25];
    float* out = (float*)d_out;

    float *B1, *B2, *XW, *B3, *H2A, *H2B;
    uint4 *WTP1, *WTP2;
    cudaGetSymbolAddress((void**)&B1, g_B1);
    cudaGetSymbolAddress((void**)&B2, g_B2);
    cudaGetSymbolAddress((void**)&XW, g_XW);
    cudaGetSymbolAddress((void**)&B3, g_B3);
    cudaGetSymbolAddress((void**)&H2A, g_H2A);
    cudaGetSymbolAddress((void**)&H2B, g_H2B);
    cudaGetSymbolAddress((void**)&WTP1, g_WTP1);
    cudaGetSymbolAddress((void**)&WTP2, g_WTP2);

    const int smem1 = (int)sizeof(ESm<8>);
    const int smem2 = (int)sizeof(ESm<36>);
    cudaFuncSetAttribute((const void*)ecc_mma_kernel<F_IN, C1, NKC1, false, 3>,
                         cudaFuncAttributeMaxDynamicSharedMemorySize, smem1);
    cudaFuncSetAttribute((const void*)ecc_mma_kernel<C1, C2, NKC2, true, 2>,
                         cudaFuncAttributeMaxDynamicSharedMemorySize, smem2);

    // side stream (capture-forked).
    cudaStream_t s1;
    cudaStreamCreateWithFlags(&s1, cudaStreamNonBlocking);
    cudaEvent_t evF, ev1, ev2, ev3;
    cudaEventCreateWithFlags(&evF, cudaEventDisableTiming);
    cudaEventCreateWithFlags(&ev1, cudaEventDisableTiming);
    cudaEventCreateWithFlags(&ev2, cudaEventDisableTiming);
    cudaEventCreateWithFlags(&ev3, cudaEventDisableTiming);

    // fork
    cudaEventRecord(evF, 0);
    cudaStreamWaitEvent(s1, evF, 0);

    // s1 branch: mlp1A first (gates ecc1), then mlp1B, then zero(out)
    mlp1_kernel<<<N_EDGES / 256, 256, 0, s1>>>(e, e1_w0, e1_b0, e1_w1, e1_b1, H2A);
    cudaEventRecord(ev1, s1);
    mlp1_kernel<<<N_EDGES / 256, 256, 0, s1>>>(e, e2_w0, e2_b0, e2_w1, e2_b1, H2B);
    cudaEventRecord(ev2, s1);
    zero_kernel<<<(G_NUM * C3 + 255) / 256, 256, 0, s1>>>(out, G_NUM * C3);
    cudaEventRecord(ev3, s1);

    // main chain on stream 0 (preps run here, overlapped with mlp1A on s1)
    prep_wt_kernel<C1, K1MAIN, K1TOT, NKC1><<<(NKC1 * C1 * 4 + 255) / 256, 256>>>(e1_wk, e1_bk, WTP1);
    prep_wt_kernel<C2, K2MAIN, K2TOT, NKC2><<<(NKC2 * C2 * 4 + 255) / 256, 256>>>(e2_wk, e2_bk, WTP2);
    base2_kernel<F_IN, C1, true><<<(N_NODES * (C1 / 4) + 255) / 256, 256>>>(x, e1_root, e1_bias, B1);
    cudaStreamWaitEvent(0, ev1, 0);
    ecc_mma_kernel<F_IN, C1, NKC1, false, 3><<<N_EDGES / 256, 256, smem1>>>(
        x, H2A, src, tgt, WTP1, B1);

    base_tile_kernel<C1, C2, true, true, false><<<N_NODES / 64, 256>>>(
        B1, e2_root, e2_bias, nullptr, B2, nullptr);
    cudaStreamWaitEvent(0, ev2, 0);
    ecc_mma_kernel<C1, C2, NKC2, true, 2><<<N_EDGES / 256, 256, smem2>>>(
        B1, H2B, src, tgt, WTP2, B2);

    base_tile_kernel<C2, C3, false, true, true><<<N_NODES / 64, 256>>>(
        B2, gcn_W, nullptr, gw + N_EDGES, XW, B3);
    gcn_edge_kernel<<<(N_EDGES * 8 + 255) / 256, 256>>>(XW, gsrc, gtgt, gw, B3);

    cudaStreamWaitEvent(0, ev3, 0);
    pool_kernel<<<(N_NODES * 8 + 255) / 256, 256>>>(B3, gcn_b, seg, out);

    cudaEventDestroy(evF); cudaEventDestroy(ev1);
    cudaEventDestroy(ev2); cudaEventDestroy(ev3);
    cudaStreamDestroy(s1);
}

// round 17
// speedup vs baseline: 1.6117x; 1.0440x over previous
#include <cuda_runtime.h>
#include <cuda_bf16.h>
#include <cstdint>

#define N_NODES 16384
#define N_EDGES 131072
#define F_IN 6
#define S_DIM 4
#define G_NUM 256
#define HH 30
#define C1 32
#define C2 64
#define C3 32

// ECC1: padded-F layout, k' = h*8 + f (f<6 real), h=30 -> bias, h=31 -> zero
#define K1PAD  256
#define NKC1   (K1PAD / 16)     // 16
// ECC2: k = h*32 + f, rows 960..991 = bias
#define K2MAIN (HH * C1)        // 960
#define K2TOT  (K2MAIN + C1)    // 992
#define K2PAD  992
#define NKC2   (K2PAD / 16)     // 62

typedef unsigned long long ull;

// ---------------- scratch (no cudaMalloc allowed) ----------------
__device__ float g_B1[N_NODES * C1];
__device__ float g_B2[N_NODES * C2];
__device__ float g_XW[N_NODES * C3];
__device__ float g_B3[N_NODES * C3];
__device__ float g_H2A[N_EDGES * 32];     // layer-1 edge MLP output (padded)
__device__ float g_H2B[N_EDGES * 32];     // layer-2 edge MLP output (padded)
__device__ uint4 g_WTP1[NKC1 * C1 * 4];   // fragment-packed {bh0,bh1,bl0,bl1}
__device__ uint4 g_WTP2[NKC2 * C2 * 4];

// ---------------- helpers ----------------
__device__ __forceinline__ void red4(float* p, float a, float b, float c, float d) {
    asm volatile("red.global.add.v4.f32 [%0], {%1, %2, %3, %4};"
                 :: "l"(p), "f"(a), "f"(b), "f"(c), "f"(d) : "memory");
}
__device__ __forceinline__ void red2(float* p, float a, float b) {
    asm volatile("red.global.add.v2.f32 [%0], {%1, %2};"
                 :: "l"(p), "f"(a), "f"(b) : "memory");
}
__device__ __forceinline__ ull pk2(float a, float b) {
    ull r; asm("mov.b64 %0, {%1, %2};" : "=l"(r) : "f"(a), "f"(b)); return r;
}
__device__ __forceinline__ void upk2(ull p, float& a, float& b) {
    asm("mov.b64 {%0, %1}, %2;" : "=f"(a), "=f"(b) : "l"(p));
}
__device__ __forceinline__ ull mul2(ull a, ull b) {
    ull r; asm("mul.rn.f32x2 %0, %1, %2;" : "=l"(r) : "l"(a), "l"(b)); return r;
}
__device__ __forceinline__ ull sub2(ull a, ull b) {
    ull r; asm("sub.rn.f32x2 %0, %1, %2;" : "=l"(r) : "l"(a), "l"(b)); return r;
}
// pack (pA -> low half, pB -> high half) as bf16x2 hi, and residual lo
__device__ __forceinline__ void splitpair(uint32_t& h, uint32_t& l, float pA, float pB) {
    asm("cvt.rn.bf16x2.f32 %0, %1, %2;" : "=r"(h) : "f"(pB), "f"(pA));
    float rA = pA - __uint_as_float(h << 16);
    float rB = pB - __uint_as_float(h & 0xffff0000u);
    asm("cvt.rn.bf16x2.f32 %0, %1, %2;" : "=r"(l) : "f"(rB), "f"(rA));
}
// same but input is a packed f32x2 product; residual via sub.f32x2
__device__ __forceinline__ void splitpk(uint32_t& h, uint32_t& l, ull p) {
    float pA, pB; upk2(p, pA, pB);
    asm("cvt.rn.bf16x2.f32 %0, %1, %2;" : "=r"(h) : "f"(pB), "f"(pA));
    float hA = __uint_as_float(h << 16);
    float hB = __uint_as_float(h & 0xffff0000u);
    ull r = sub2(p, pk2(hA, hB));
    float rA, rB; upk2(r, rA, rB);
    asm("cvt.rn.bf16x2.f32 %0, %1, %2;" : "=r"(l) : "f"(rB), "f"(rA));
}
__device__ __forceinline__ void mma_bf16(float* c, const uint32_t* a, uint32_t b0, uint32_t b1) {
    asm volatile("mma.sync.aligned.m16n8k16.row.col.f32.bf16.bf16.f32 "
                 "{%0,%1,%2,%3}, {%4,%5,%6,%7}, {%8,%9}, {%0,%1,%2,%3};"
                 : "+f"(c[0]), "+f"(c[1]), "+f"(c[2]), "+f"(c[3])
                 : "r"(a[0]), "r"(a[1]), "r"(a[2]), "r"(a[3]), "r"(b0), "r"(b1));
}

// ---------------- weight prep: ECC2 layout (k = h*C1 + f, bias appended) ----------------
template <int C, int KMAIN, int KTOT, int NKC>
__global__ void prep_wt_kernel(const float* __restrict__ wk, const float* __restrict__ bk,
                               uint4* __restrict__ out)
{
    int idx = blockIdx.x * 256 + threadIdx.x;
    if (idx >= NKC * C * 4) return;
    int kc = idx / (C * 4);
    int rem = idx - kc * (C * 4);
    int c = rem >> 2, q = rem & 3;
    int k0 = kc * 16 + q * 2;
    float v[4];
    #pragma unroll
    for (int t = 0; t < 4; t++) {
        int k = k0 + (t >> 1) * 8 + (t & 1);
        float x = 0.f;
        if (k < KMAIN)      x = __ldg(wk + (size_t)k * C + c);
        else if (k < KTOT)  x = __ldg(bk + (size_t)(k - KMAIN) * C + c);
        v[t] = x;
    }
    uint4 o;
    splitpair(o.x, o.z, v[0], v[1]);
    splitpair(o.y, o.w, v[2], v[3]);
    out[idx] = o;
}

// ---------------- weight prep: ECC1 padded-F layout (k' = h*8 + f) ----------------
template <int C, int F, int NKC>
__global__ void prep_wt_pad8_kernel(const float* __restrict__ wk, const float* __restrict__ bk,
                                    uint4* __restrict__ out)
{
    int idx = blockIdx.x * 256 + threadIdx.x;
    if (idx >= NKC * C * 4) return;
    int kc = idx / (C * 4);
    int rem = idx - kc * (C * 4);
    int c = rem >> 2, q = rem & 3;
    int k0 = kc * 16 + q * 2;
    float v[4];
    #pragma unroll
    for (int t = 0; t < 4; t++) {
        int k = k0 + (t >> 1) * 8 + (t & 1);
        int h = k >> 3, f = k & 7;
        float x = 0.f;
        if (f < F) {
            if (h < HH)       x = __ldg(wk + (size_t)(h * F + f) * C + c);
            else if (h == HH) x = __ldg(bk + (size_t)f * C + c);
        }
        v[t] = x;
    }
    uint4 o;
    splitpair(o.x, o.z, v[0], v[1]);
    splitpair(o.y, o.w, v[2], v[3]);
    out[idx] = o;
}

// ---------------- per-layer edge MLP: h2 = relu(relu(e@w0+b0)@w1+b1) ----------------
struct M1Sm {
    float w0p[S_DIM * 32];
    float b0p[32];
    float b1p[32];
    float w1p[HH * 32];
};

__global__ __launch_bounds__(256) void mlp1_kernel(
    const float* __restrict__ e,
    const float* __restrict__ w0, const float* __restrict__ b0,
    const float* __restrict__ w1, const float* __restrict__ b1,
    float* __restrict__ h2g)
{
    __shared__ M1Sm S;
    const int tid = threadIdx.x;
    for (int j = tid; j < S_DIM * 32; j += 256) {
        int s = j >> 5, jj = j & 31;
        S.w0p[j] = (jj < HH) ? w0[s * HH + jj] : 0.f;
    }
    for (int j = tid; j < HH * 32; j += 256) {
        int h = j >> 5, jj = j & 31;
        S.w1p[j] = (jj < HH) ? w1[h * HH + jj] : 0.f;
    }
    if (tid < 32) {
        S.b0p[tid] = (tid < HH) ? b0[tid] : 0.f;
        S.b1p[tid] = (tid < HH) ? b1[tid] : 0.f;
    }
    __syncthreads();

    const int i = blockIdx.x * 256 + tid;
    float4 ef = __ldg((const float4*)e + i);
    float ev[4] = {ef.x, ef.y, ef.z, ef.w};

    float h1[32];
    #pragma unroll
    for (int jb = 0; jb < 8; jb++) {
        float4 a = *(const float4*)&S.b0p[jb * 4];
        #pragma unroll
        for (int s = 0; s < S_DIM; s++) {
            float4 w = *(const float4*)&S.w0p[s * 32 + jb * 4];
            a.x += ev[s] * w.x; a.y += ev[s] * w.y;
            a.z += ev[s] * w.z; a.w += ev[s] * w.w;
        }
        h1[jb * 4 + 0] = fmaxf(a.x, 0.f); h1[jb * 4 + 1] = fmaxf(a.y, 0.f);
        h1[jb * 4 + 2] = fmaxf(a.z, 0.f); h1[jb * 4 + 3] = fmaxf(a.w, 0.f);
    }
    float* dst = h2g + (size_t)i * 32;
    #pragma unroll
    for (int jb = 0; jb < 8; jb++) {
        float4 a = *(const float4*)&S.b1p[jb * 4];
        #pragma unroll
        for (int h = 0; h < HH; h++) {
            float4 w = *(const float4*)&S.w1p[h * 32 + jb * 4];
            a.x += h1[h] * w.x; a.y += h1[h] * w.y;
            a.z += h1[h] * w.z; a.w += h1[h] * w.w;
        }
        *(float4*)(dst + jb * 4) = make_float4(fmaxf(a.x, 0.f), fmaxf(a.y, 0.f),
                                               fmaxf(a.z, 0.f), fmaxf(a.w, 0.f));
    }
}

// ---------------- ECC layer: h2-tile load + gather + bf16 3-MMA GEMM + scatter ----------------
// h2 tile is padded: col 30 = 1.0 (bias rows), col 31 = 0 (pad). A-fragments built as
// h2x[h]*xs pair products; FP=8: chunk kc covers h = 2kc, 2kc+1; FP=32: h = kc>>1.
template <int XSTR>
struct ESm {
    float h2[256 * 36];
    float xs[256 * XSTR];
};

template <int F, int FP, int C, int NKC, bool RELU_IN, int MINCTA>
__global__ __launch_bounds__(256, MINCTA) void ecc_mma_kernel(
    const float* __restrict__ xin, const float* __restrict__ h2g,
    const int* __restrict__ src, const int* __restrict__ tgt,
    const uint4* __restrict__ wtp,
    float* __restrict__ agg)
{
    constexpr int NT = 256, TM = 256;
    constexpr int XSTR = (FP == 32) ? 36 : 8;
    constexpr int NNT = C / 8;

    extern __shared__ __align__(16) char smraw[];
    ESm<XSTR>& S = *reinterpret_cast<ESm<XSTR>*>(smraw);

    const int tid = threadIdx.x;
    const int i0 = blockIdx.x * TM;

    // --- load h2 tile (coalesced; col 30 -> 1.0, col 31 stays 0) ---
    #pragma unroll
    for (int t = 0; t < 8; t++) {
        int j = tid + t * NT;
        int i = j >> 3, q = j & 7;
        float4 v = __ldg((const float4*)(h2g + (size_t)(i0 + i) * 32) + q);
        if (q == 7) v.z = 1.0f;                 // h2x[30] = 1 (bias row scalar)
        *(float4*)&S.h2[i * 36 + q * 4] = v;
    }
    // --- gather x[src] ---
    if constexpr (FP == 32) {
        #pragma unroll
        for (int t = 0; t < 8; t++) {
            int j = tid + t * NT;
            int i = j >> 3, q = j & 7;
            int s = __ldg(src + i0 + i);
            float4 v = __ldg((const float4*)(xin + (size_t)s * F) + q);
            if (RELU_IN) { v.x = fmaxf(v.x, 0.f); v.y = fmaxf(v.y, 0.f);
                           v.z = fmaxf(v.z, 0.f); v.w = fmaxf(v.w, 0.f); }
            *(float4*)(S.xs + i * XSTR + q * 4) = v;
        }
    } else {
        // F=6 padded into stride-8 rows; f=6,7 zero
        #pragma unroll
        for (int t = 0; t < (TM * 8) / NT; t++) {
            int j = tid + t * NT;
            int i = j >> 3, f = j & 7;
            float v = 0.f;
            if (f < F) {
                int s = __ldg(src + i0 + i);
                v = __ldg(xin + (size_t)s * F + f);
                if (RELU_IN) v = fmaxf(v, 0.f);
            }
            S.xs[i * 8 + f] = v;
        }
    }
    __syncthreads();

    // --- warp-tile GEMM: warp covers rows [32w, 32w+32) x all C (2 m16 tiles) ---
    const int lane = tid & 31, wid = tid >> 5;
    const int qr = lane >> 2;
    const int kq = lane & 3;
    const int ka = kq * 2;
    const int rr[4] = { wid * 32 + qr, wid * 32 + qr + 8,
                        wid * 32 + qr + 16, wid * 32 + qr + 24 };

    float acc[2][NNT][4];
    #pragma unroll
    for (int m = 0; m < 2; m++)
        #pragma unroll
        for (int nt = 0; nt < NNT; nt++) {
            acc[m][nt][0] = 0.f; acc[m][nt][1] = 0.f;
            acc[m][nt][2] = 0.f; acc[m][nt][3] = 0.f;
        }

    #pragma unroll 2
    for (int kc = 0; kc < NKC; kc++) {
        uint32_t ah[2][4], al[2][4];
        if constexpr (FP == 32) {
            const int hcol = kc >> 1;
            const int f0 = (kc & 1) * 16;
            #pragma unroll
            for (int m = 0; m < 2; m++) {
                float h0 = S.h2[rr[2 * m] * 36 + hcol];
                float h1 = S.h2[rr[2 * m + 1] * 36 + hcol];
                ull hs0 = pk2(h0, h0), hs1 = pk2(h1, h1);
                ull xa0 = *(const ull*)(S.xs + rr[2 * m] * XSTR + f0 + ka);
                ull xa8 = *(const ull*)(S.xs + rr[2 * m] * XSTR + f0 + ka + 8);
                ull xb0 = *(const ull*)(S.xs + rr[2 * m + 1] * XSTR + f0 + ka);
                ull xb8 = *(const ull*)(S.xs + rr[2 * m + 1] * XSTR + f0 + ka + 8);
                splitpk(ah[m][0], al[m][0], mul2(hs0, xa0));
                splitpk(ah[m][1], al[m][1], mul2(hs1, xb0));
                splitpk(ah[m][2], al[m][2], mul2(hs0, xa8));
                splitpk(ah[m][3], al[m][3], mul2(hs1, xb8));
            }
        } else {
            // FP=8: chunk kc covers h = 2kc (first 8 k's) and h = 2kc+1 (second 8)
            #pragma unroll
            for (int m = 0; m < 2; m++) {
                ull hp0 = *(const ull*)(S.h2 + rr[2 * m] * 36 + 2 * kc);      // {h2[2kc], h2[2kc+1]}
                ull hp1 = *(const ull*)(S.h2 + rr[2 * m + 1] * 36 + 2 * kc);
                float h00, h01, h10, h11;
                upk2(hp0, h00, h01);
                upk2(hp1, h10, h11);
                ull x0 = *(const ull*)(S.xs + rr[2 * m] * 8 + ka);
                ull x1 = *(const ull*)(S.xs + rr[2 * m + 1] * 8 + ka);
                splitpk(ah[m][0], al[m][0], mul2(pk2(h00, h00), x0));
                splitpk(ah[m][1], al[m][1], mul2(pk2(h10, h10), x1));
                splitpk(ah[m][2], al[m][2], mul2(pk2(h01, h01), x0));
                splitpk(ah[m][3], al[m][3], mul2(pk2(h11, h11), x1));
            }
        }

        #pragma unroll
        for (int nt = 0; nt < NNT; nt++) {
            uint4 bf = __ldg(&wtp[(size_t)(kc * C + nt * 8 + qr) * 4 + kq]);
            #pragma unroll
            for (int m = 0; m < 2; m++) {
                mma_bf16(acc[m][nt], ah[m], bf.x, bf.y);
                mma_bf16(acc[m][nt], al[m], bf.x, bf.y);
                mma_bf16(acc[m][nt], ah[m], bf.z, bf.w);
            }
        }
    }

    // --- scatter-add to agg[tgt] ---
    #pragma unroll
    for (int m = 0; m < 2; m++) {
        int t0 = __ldg(tgt + i0 + rr[2 * m]);
        int t1 = __ldg(tgt + i0 + rr[2 * m + 1]);
        float* d0 = agg + (size_t)t0 * C + ka;
        float* d1 = agg + (size_t)t1 * C + ka;
        #pragma unroll
        for (int nt = 0; nt < NNT; nt++) {
            red2(d0 + nt * 8, acc[m][nt][0], acc[m][nt][1]);
            red2(d1 + nt * 8, acc[m][nt][2], acc[m][nt][3]);
        }
    }
}

// ---------------- staged node GEMM (F%4==0): out = [bias] + relu?(x)@root; opt. self-loop ----------------
template <int F, int C, bool BIAS, bool RELU_IN, bool SELF>
__global__ __launch_bounds__(256) void base_tile_kernel(
    const float* __restrict__ x, const float* __restrict__ root,
    const float* __restrict__ bias, const float* __restrict__ gw_self,
    float* __restrict__ out, float* __restrict__ b3)
{
    constexpr int NB = 64;
    constexpr int XP = F + 1;
    __shared__ float sx[NB * XP];
    __shared__ float sroot[F * C];
    __shared__ float sb[C];
    const int tid = threadIdx.x;
    const int n0 = blockIdx.x * NB;

    for (int j = tid; j < F * C; j += 256) sroot[j] = root[j];
    if (BIAS) { if (tid < C) sb[tid] = bias[tid]; }
    for (int j = tid; j < NB * (F / 4); j += 256) {
        int n = j / (F / 4), q = j - n * (F / 4);
        float4 v = __ldg((const float4*)(x + (size_t)(n0 + n) * F) + q);
        if (RELU_IN) { v.x = fmaxf(v.x, 0.f); v.y = fmaxf(v.y, 0.f);
                       v.z = fmaxf(v.z, 0.f); v.w = fmaxf(v.w, 0.f); }
        float* d = sx + n * XP + q * 4;
        d[0] = v.x; d[1] = v.y; d[2] = v.z; d[3] = v.w;
    }
    __syncthreads();

    for (int j = tid; j < NB * (C / 4); j += 256) {
        int n = j / (C / 4), q = (j - n * (C / 4)) * 4;
        float4 a = BIAS ? make_float4(sb[q], sb[q + 1], sb[q + 2], sb[q + 3])
                        : make_float4(0.f, 0.f, 0.f, 0.f);
        const float* xr = sx + n * XP;
        #pragma unroll
        for (int f = 0; f < F; f++) {
            float xv = xr[f];
            float4 rv = *(const float4*)&sroot[f * C + q];
            a.x += xv * rv.x; a.y += xv * rv.y; a.z += xv * rv.z; a.w += xv * rv.w;
        }
        *(float4*)(out + (size_t)(n0 + n) * C + q) = a;
        if (SELF) {
            float w = __ldg(gw_self + n0 + n);
            *(float4*)(b3 + (size_t)(n0 + n) * C + q) =
                make_float4(w * a.x, w * a.y, w * a.z, w * a.w);
        }
    }
}

// ---------------- simple node GEMM (F=6 case) ----------------
template <int F, int C, bool BIAS>
__global__ __launch_bounds__(256) void base2_kernel(
    const float* __restrict__ x, const float* __restrict__ root,
    const float* __restrict__ bias, float* __restrict__ out)
{
    __shared__ float sroot[F * C];
    __shared__ float sb[C];
    const int tid = threadIdx.x;
    for (int j = tid; j < F * C; j += 256) sroot[j] = root[j];
    if (BIAS) { if (tid < C) sb[tid] = bias[tid]; }
    __syncthreads();

    constexpr int QC = C / 4;
    int idx = blockIdx.x * 256 + tid;
    int n = idx / QC, q = (idx - n * QC) * 4;
    if (n >= N_NODES) return;

    float4 a = BIAS ? make_float4(sb[q], sb[q + 1], sb[q + 2], sb[q + 3])
                    : make_float4(0.f, 0.f, 0.f, 0.f);
    const float* xr = x + (size_t)n * F;
    #pragma unroll
    for (int f = 0; f < F; f++) {
        float xv = __ldg(xr + f);
        float4 rv = *(const float4*)&sroot[f * C + q];
        a.x += xv * rv.x; a.y += xv * rv.y; a.z += xv * rv.z; a.w += xv * rv.w;
    }
    *(float4*)(out + (size_t)n * C + q) = a;
}

__global__ void zero_kernel(float* __restrict__ buf, int n)
{
    int i = blockIdx.x * blockDim.x + threadIdx.x;
    if (i < n) buf[i] = 0.f;
}

// GCN weighted SpMM over real edges only (self loops fused into XW kernel)
__global__ void gcn_edge_kernel(const float* __restrict__ xw,
                                const int* __restrict__ gs, const int* __restrict__ gt,
                                const float* __restrict__ gw, float* __restrict__ b3)
{
    int idx = blockIdx.x * blockDim.x + threadIdx.x;
    int m = idx >> 3, q = (idx & 7) * 4;
    if (m >= N_EDGES) return;
    float w = __ldg(gw + m);
    float4 v = __ldg((const float4*)(xw + (size_t)__ldg(gs + m) * C3 + q));
    red4(b3 + (size_t)__ldg(gt + m) * C3 + q, w * v.x, w * v.y, w * v.z, w * v.w);
}

// x3 = relu(b3 + gcn_b); out[seg[n], :] += x3[n, :]
__global__ void pool_kernel(const float* __restrict__ b3, const float* __restrict__ gb,
                            const int* __restrict__ seg, float* __restrict__ out)
{
    int idx = blockIdx.x * blockDim.x + threadIdx.x;
    int n = idx >> 3, q = (idx & 7) * 4;
    if (n >= N_NODES) return;
    float4 v = *(const float4*)(b3 + (size_t)n * C3 + q);
    float a = fmaxf(v.x + __ldg(gb + q), 0.f);
    float b = fmaxf(v.y + __ldg(gb + q + 1), 0.f);
    float c = fmaxf(v.z + __ldg(gb + q + 2), 0.f);
    float d = fmaxf(v.w + __ldg(gb + q + 3), 0.f);
    red4(out + (size_t)__ldg(seg + n) * C3 + q, a, b, c, d);
}

// ---------------- launch ----------------
extern "C" void kernel_launch(void* const* d_in, const int* in_sizes, int n_in,
                              void* d_out, int out_size)
{
    (void)in_sizes; (void)n_in; (void)out_size;
    const float* x     = (const float*)d_in[0];
    const float* e     = (const float*)d_in[1];
    const int*   src   = (const int*)d_in[2];
    const int*   tgt   = (const int*)d_in[3];
    const int*   seg   = (const int*)d_in[4];
    const int*   gsrc  = (const int*)d_in[5];
    const int*   gtgt  = (const int*)d_in[6];
    const float* gw    = (const float*)d_in[7];
    const float* e1_w0 = (const float*)d_in[8];
    const float* e1_b0 = (const float*)d_in[9];
    const float* e1_w1 = (const float*)d_in[10];
    const float* e1_b1 = (const float*)d_in[11];
    const float* e1_wk = (const float*)d_in[12];
    const float* e1_bk = (const float*)d_in[13];
    const float* e1_root = (const float*)d_in[14];
    const float* e1_bias = (const float*)d_in[15];
    const float* e2_w0 = (const float*)d_in[16];
    const float* e2_b0 = (const float*)d_in[17];
    const float* e2_w1 = (const float*)d_in[18];
    const float* e2_b1 = (const float*)d_in[19];
    const float* e2_wk = (const float*)d_in[20];
    const float* e2_bk = (const float*)d_in[21];
    const float* e2_root = (const float*)d_in[22];
    const float* e2_bias = (const float*)d_in[23];
    const float* gcn_W = (const float*)d_in[24];
    const float* gcn_b = (const float*)d_in[25];
    float* out = (float*)d_out;

    float *B1, *B2, *XW, *B3, *H2A, *H2B;
    uint4 *WTP1, *WTP2;
    cudaGetSymbolAddress((void**)&B1, g_B1);
    cudaGetSymbolAddress((void**)&B2, g_B2);
    cudaGetSymbolAddress((void**)&XW, g_XW);
    cudaGetSymbolAddress((void**)&B3, g_B3);
    cudaGetSymbolAddress((void**)&H2A, g_H2A);
    cudaGetSymbolAddress((void**)&H2B, g_H2B);
    cudaGetSymbolAddress((void**)&WTP1, g_WTP1);
    cudaGetSymbolAddress((void**)&WTP2, g_WTP2);

    const int smem1 = (int)sizeof(ESm<8>);
    const int smem2 = (int)sizeof(ESm<36>);
    cudaFuncSetAttribute((const void*)ecc_mma_kernel<F_IN, 8, C1, NKC1, false, 3>,
                         cudaFuncAttributeMaxDynamicSharedMemorySize, smem1);
    cudaFuncSetAttribute((const void*)ecc_mma_kernel<C1, 32, C2, NKC2, true, 2>,
                         cudaFuncAttributeMaxDynamicSharedMemorySize, smem2);

    // side stream (capture-forked).
    cudaStream_t s1;
    cudaStreamCreateWithFlags(&s1, cudaStreamNonBlocking);
    cudaEvent_t evF, ev1, ev2, ev3;
    cudaEventCreateWithFlags(&evF, cudaEventDisableTiming);
    cudaEventCreateWithFlags(&ev1, cudaEventDisableTiming);
    cudaEventCreateWithFlags(&ev2, cudaEventDisableTiming);
    cudaEventCreateWithFlags(&ev3, cudaEventDisableTiming);

    // fork
    cudaEventRecord(evF, 0);
    cudaStreamWaitEvent(s1, evF, 0);

    // s1 branch: mlp1A first (gates ecc1), then mlp1B, then zero(out)
    mlp1_kernel<<<N_EDGES / 256, 256, 0, s1>>>(e, e1_w0, e1_b0, e1_w1, e1_b1, H2A);
    cudaEventRecord(ev1, s1);
    mlp1_kernel<<<N_EDGES / 256, 256, 0, s1>>>(e, e2_w0, e2_b0, e2_w1, e2_b1, H2B);
    cudaEventRecord(ev2, s1);
    zero_kernel<<<(G_NUM * C3 + 255) / 256, 256, 0, s1>>>(out, G_NUM * C3);
    cudaEventRecord(ev3, s1);

    // main chain on stream 0 (preps run here, overlapped with mlp1A on s1)
    prep_wt_pad8_kernel<C1, F_IN, NKC1><<<(NKC1 * C1 * 4 + 255) / 256, 256>>>(e1_wk, e1_bk, WTP1);
    prep_wt_kernel<C2, K2MAIN, K2TOT, NKC2><<<(NKC2 * C2 * 4 + 255) / 256, 256>>>(e2_wk, e2_bk, WTP2);
    base2_kernel<F_IN, C1, true><<<(N_NODES * (C1 / 4) + 255) / 256, 256>>>(x, e1_root, e1_bias, B1);
    cudaStreamWaitEvent(0, ev1, 0);
    ecc_mma_kernel<F_IN, 8, C1, NKC1, false, 3><<<N_EDGES / 256, 256, smem1>>>(
        x, H2A, src, tgt, WTP1, B1);

    base_tile_kernel<C1, C2, true, true, false><<<N_NODES / 64, 256>>>(
        B1, e2_root, e2_bias, nullptr, B2, nullptr);
    cudaStreamWaitEvent(0, ev2, 0);
    ecc_mma_kernel<C1, 32, C2, NKC2, true, 2><<<N_EDGES / 256, 256, smem2>>>(
        B1, H2B, src, tgt, WTP2, B2);

    base_tile_kernel<C2, C3, false, true, true><<<N_NODES / 64, 256>>>(
        B2, gcn_W, nullptr, gw + N_EDGES, XW, B3);
    gcn_edge_kernel<<<(N_EDGES * 8 + 255) / 256, 256>>>(XW, gsrc, gtgt, gw, B3);

    cudaStreamWaitEvent(0, ev3, 0);
    pool_kernel<<<(N_NODES * 8 + 255) / 256, 256>>>(B3, gcn_b, seg, out);

    cudaEventDestroy(evF); cudaEventDestroy(ev1);
    cudaEventDestroy(ev2); cudaEventDestroy(ev3);
    cudaStreamDestroy(s1);
}